// round 4
// baseline (speedup 1.0000x reference)
#include <cuda_runtime.h>

// Tridiagonal Thomas solve with precomputed LU factors, chunked with
// exponential-decay halos (|c|,|w| <= 1/3  =>  (1/3)^32 ~ 5e-16 warmup error).
//
// Layout: block = RPB rows x one L_CHUNK-column chunk (+HALO each side).
// Tile staged in smem (coalesced), each thread solves one row slice in place.

#define L_CHUNK 128
#define HALO    32
#define CW      (L_CHUNK + 2 * HALO)   // 192 columns max per tile
#define RPB     128                    // rows per block == threads per block
#define TS      196                    // tile row stride (floats): CW + 4 pad -> conflict-free .128
#define MAXN    8192

__device__ float g_cc[MAXN];   // cc[i] = c[i-1], cc[0] = 0
__device__ float g_ia[MAXN];   // 1 / a[i]
__device__ float g_w [MAXN];   // b[i] / a[i], w[N-1] = 0

__global__ void setup_coeffs(const float* __restrict__ a,
                             const float* __restrict__ b,
                             const float* __restrict__ c, int N) {
    int i = blockIdx.x * blockDim.x + threadIdx.x;
    if (i < N) {
        g_cc[i] = (i == 0) ? 0.0f : c[i - 1];
        float ia = 1.0f / a[i];
        g_ia[i] = ia;
        g_w[i]  = (i < N - 1) ? b[i] * ia : 0.0f;
    }
}

__global__ void __launch_bounds__(RPB, 2)
solve_kernel(const float* __restrict__ x, float* __restrict__ z, int N) {
    extern __shared__ float smem[];
    float* tile = smem;                    // [RPB][TS]
    float* cc_s = smem + RPB * TS;         // [CW]
    float* ia_s = cc_s + CW;               // [CW]
    float* w_s  = ia_s + CW;               // [CW]

    const int tid  = threadIdx.x;
    const int s    = blockIdx.x * L_CHUNK;          // chunk start
    const int c0   = max(s - HALO, 0);              // tile col range [c0, c1)
    const int c1   = min(s + L_CHUNK + HALO, N);
    const int ncol = c1 - c0;                       // 160 or 192, multiple of 4
    const int jlo  = s - c0;                        // 0 (first chunk) or 32
    const int r0   = blockIdx.y * RPB;

    // Stage coefficients (uniform across rows; amortized over 128 rows).
    for (int j = tid; j < ncol; j += RPB) {
        int gi = c0 + j;
        cc_s[j] = g_cc[gi];
        ia_s[j] = g_ia[gi];
        w_s[j]  = g_w[gi];
    }

    // Load tile, coalesced: lanes -> consecutive columns of a row.
    {
        const float* xb = x + (size_t)r0 * N + c0;
        #pragma unroll 4
        for (int row = 0; row < RPB; ++row) {
            float* tr = tile + row * TS;
            const float* xr = xb + (size_t)row * N;
            for (int col = tid; col < ncol; col += RPB)
                tr[col] = xr[col];
        }
    }
    __syncthreads();

    // Per-thread row solve, fully in place in the tile row.
    {
        float* tr = tile + tid * TS;

        // Forward: y[i] = x[i] - y[i-1]*cc[i]; store u = y * (1/a) (off-chain mul).
        float y = 0.0f;   // exact for c0==0 (cc[0]=0); halo-warmed otherwise
        #pragma unroll 2
        for (int j = 0; j < ncol; j += 4) {
            float4 xv = *(const float4*)(tr + j);
            float4 cv = *(const float4*)(cc_s + j);
            float4 iv = *(const float4*)(ia_s + j);
            float4 u;
            y = fmaf(-y, cv.x, xv.x); u.x = y * iv.x;
            y = fmaf(-y, cv.y, xv.y); u.y = y * iv.y;
            y = fmaf(-y, cv.z, xv.z); u.z = y * iv.z;
            y = fmaf(-y, cv.w, xv.w); u.w = y * iv.w;
            *(float4*)(tr + j) = u;
        }

        // Backward: z[i] = u[i] - w[i]*z[i+1]  (single-FMA 4-cycle chain).
        float zv = 0.0f;  // exact for c1==N (w[N-1]=0); halo-warmed otherwise
        #pragma unroll 2
        for (int j = ncol - 4; j >= jlo; j -= 4) {
            float4 uv = *(const float4*)(tr + j);
            float4 wv = *(const float4*)(w_s + j);
            float4 zo;
            zv = fmaf(-zv, wv.w, uv.w); zo.w = zv;
            zv = fmaf(-zv, wv.z, uv.z); zo.z = zv;
            zv = fmaf(-zv, wv.y, uv.y); zo.y = zv;
            zv = fmaf(-zv, wv.x, uv.x); zo.x = zv;
            *(float4*)(tr + j) = zo;
        }
    }
    __syncthreads();

    // Store chunk columns [jlo, jlo + Lw), coalesced.
    {
        const int Lw = min(L_CHUNK, N - s);
        float* zb = z + (size_t)r0 * N + s;
        #pragma unroll 4
        for (int row = 0; row < RPB; ++row) {
            const float* tr = tile + row * TS + jlo;
            float* zr = zb + (size_t)row * N;
            for (int col = tid; col < Lw; col += RPB)
                zr[col] = tr[col];
        }
    }
}

extern "C" void kernel_launch(void* const* d_in, const int* in_sizes, int n_in,
                              void* d_out, int out_size) {
    const float* x = (const float*)d_in[0];
    const float* a = (const float*)d_in[1];
    const float* b = (const float*)d_in[2];
    const float* c = (const float*)d_in[3];
    float* z = (float*)d_out;

    const int N = in_sizes[1];          // 8192 (length of a)
    const int B = in_sizes[0] / N;      // 4096

    setup_coeffs<<<(N + 255) / 256, 256>>>(a, b, c, N);

    const int smemBytes = (RPB * TS + 3 * CW) * (int)sizeof(float);  // 102656 B
    cudaFuncSetAttribute(solve_kernel,
                         cudaFuncAttributeMaxDynamicSharedMemorySize, smemBytes);

    dim3 grid(N / L_CHUNK, B / RPB);    // 64 x 32 = 2048 blocks
    solve_kernel<<<grid, RPB, smemBytes>>>(x, z, N);
}

// round 7
// speedup vs baseline: 10.0130x; 10.0130x over previous
#include <cuda_runtime.h>
#include <cstdint>

// Tridiagonal Thomas solve with precomputed LU factors, chunked with
// exponential-decay halos. Factor magnitudes |c|,|w| <= 1/3 (typ 0.268),
// so a 16-element warmup halo carries error ~0.268^16 ~ 7e-10 — far below
// fp32 noise. Each block: 64 rows x (128 + 2*16) columns, tile staged to
// smem via cp.async (full-tile MLP), per-thread in-place row solve,
// vectorized float4 store of the interior 128 columns.

#define L_CHUNK 128
#define HALO    16
#define CW      (L_CHUNK + 2 * HALO)   // 160 columns max per tile
#define RPB     64                     // rows per block == threads per block
#define TS      164                    // tile row stride: 164/4=41 odd -> conflict-free .128
#define MAXN    8192

__device__ float g_cc[MAXN];   // cc[i] = c[i-1], cc[0] = 0
__device__ float g_ia[MAXN];   // 1 / a[i]
__device__ float g_w [MAXN];   // b[i] / a[i], w[N-1] = 0

__global__ void setup_coeffs(const float* __restrict__ a,
                             const float* __restrict__ b,
                             const float* __restrict__ c, int N) {
    int i = blockIdx.x * blockDim.x + threadIdx.x;
    if (i < N) {
        g_cc[i] = (i == 0) ? 0.0f : c[i - 1];
        float ia = 1.0f / a[i];
        g_ia[i] = ia;
        g_w[i]  = (i < N - 1) ? b[i] * ia : 0.0f;
    }
}

__device__ __forceinline__ uint32_t smem_u32(const void* p) {
    return (uint32_t)__cvta_generic_to_shared(p);
}

__global__ void __launch_bounds__(RPB)
solve_kernel(const float* __restrict__ x, float* __restrict__ z, int N) {
    __shared__ float tile[RPB * TS];   // 64*164*4 = 41.0 KB
    __shared__ float cc_s[CW], ia_s[CW], w_s[CW];

    const int tid  = threadIdx.x;
    const int lane = tid & 31;
    const int warp = tid >> 5;
    const int s    = blockIdx.x * L_CHUNK;          // chunk start
    const int c0   = max(s - HALO, 0);              // tile col range [c0, c1)
    const int c1   = min(s + L_CHUNK + HALO, N);
    const int ncol = c1 - c0;                       // 144 or 160, multiple of 4
    const int nf4  = ncol >> 2;                     // 36 or 40 float4 per row
    const int jlo  = s - c0;                        // 0 (first chunk) or 16
    const int r0   = blockIdx.y * RPB;

    // Stage coefficients (L2-broadcast across all blocks, cheap).
    for (int j = tid; j < ncol; j += RPB) {
        int gi = c0 + j;
        cc_s[j] = g_cc[gi];
        ia_s[j] = g_ia[gi];
        w_s[j]  = g_w[gi];
    }

    // Async tile load: whole tile in flight before any wait (max MLP).
    {
        const float* xb = x + (size_t)r0 * N + c0;
        #pragma unroll 4
        for (int r = warp; r < RPB; r += RPB / 32) {
            const float* xr = xb + (size_t)r * N;
            uint32_t dst_row = smem_u32(tile + r * TS);
            for (int c4 = lane; c4 < nf4; c4 += 32) {
                asm volatile("cp.async.cg.shared.global [%0], [%1], 16;\n"
                             :: "r"(dst_row + c4 * 16), "l"(xr + c4 * 4));
            }
        }
        asm volatile("cp.async.commit_group;\n" ::: "memory");
        asm volatile("cp.async.wait_group 0;\n" ::: "memory");
    }
    __syncthreads();

    // Per-thread row solve, fully in place in the tile row.
    {
        float* tr = tile + tid * TS;

        // Forward: y[i] = x[i] - y[i-1]*cc[i]; store u = y/a (off-chain mul).
        float y = 0.0f;   // exact for c0==0 (cc[0]=0); halo-warmed otherwise
        #pragma unroll 4
        for (int j = 0; j < ncol; j += 4) {
            float4 xv = *(const float4*)(tr + j);
            float4 cv = *(const float4*)(cc_s + j);
            float4 iv = *(const float4*)(ia_s + j);
            float4 u;
            y = fmaf(-y, cv.x, xv.x); u.x = y * iv.x;
            y = fmaf(-y, cv.y, xv.y); u.y = y * iv.y;
            y = fmaf(-y, cv.z, xv.z); u.z = y * iv.z;
            y = fmaf(-y, cv.w, xv.w); u.w = y * iv.w;
            *(float4*)(tr + j) = u;
        }

        // Backward: z[i] = u[i] - w[i]*z[i+1]  (single-FMA 4-cycle chain).
        float zv = 0.0f;  // exact for c1==N (w[N-1]=0); halo-warmed otherwise
        #pragma unroll 4
        for (int j = ncol - 4; j >= jlo; j -= 4) {
            float4 uv = *(const float4*)(tr + j);
            float4 wv = *(const float4*)(w_s + j);
            float4 zo;
            zv = fmaf(-zv, wv.w, uv.w); zo.w = zv;
            zv = fmaf(-zv, wv.z, uv.z); zo.z = zv;
            zv = fmaf(-zv, wv.y, uv.y); zo.y = zv;
            zv = fmaf(-zv, wv.x, uv.x); zo.x = zv;
            *(float4*)(tr + j) = zo;
        }
    }
    __syncthreads();

    // Vectorized store of interior columns [jlo, jlo+128): 32 float4/row.
    // Warp-per-row mapping: iteration i -> row i>>5, col4 i&31.
    // STG.128 coalesced (512B/warp), LDS.128 conflict-free (TS/4 odd).
    {
        float* zb = z + (size_t)r0 * N + s;
        const int nout = RPB * (L_CHUNK / 4);
        #pragma unroll 8
        for (int i = tid; i < nout; i += RPB) {
            int row = i >> 5;
            int c4  = i & 31;
            float4 v = *(const float4*)(tile + row * TS + jlo + c4 * 4);
            *(float4*)(zb + (size_t)row * N + c4 * 4) = v;
        }
    }
}

extern "C" void kernel_launch(void* const* d_in, const int* in_sizes, int n_in,
                              void* d_out, int out_size) {
    const float* x = (const float*)d_in[0];
    const float* a = (const float*)d_in[1];
    const float* b = (const float*)d_in[2];
    const float* c = (const float*)d_in[3];
    float* z = (float*)d_out;

    const int N = in_sizes[1];          // 8192
    const int B = in_sizes[0] / N;      // 4096

    setup_coeffs<<<(N + 255) / 256, 256>>>(a, b, c, N);

    dim3 grid(N / L_CHUNK, B / RPB);    // 64 x 64 = 4096 blocks
    solve_kernel<<<grid, RPB>>>(x, z, N);
}

// round 9
// speedup vs baseline: 12.9514x; 1.2935x over previous
#include <cuda_runtime.h>
#include <cstdint>

// Tridiagonal Thomas solve with precomputed LU factors, chunked with
// exponential-decay halos (|c|,|w| <= 1/3 => 0.268^16 ~ 7e-10 warmup error).
//
// Design: one block == one warp == a fully independent pipeline.
// 32 rows x (128 + 2*16) columns per block, ~23 KB smem -> 9 resident
// blocks/SM, each running load(cp.async) -> compute -> store with only
// __syncwarp()s. No __syncthreads anywhere: 9 decorrelated pipelines per SM
// keep HBM demand continuous instead of phase-bursty.

#define L_CHUNK 128
#define HALO    16
#define CW      (L_CHUNK + 2 * HALO)   // 160 columns max per tile
#define ROWS    32                     // rows per block == threads per block
#define TS      164                    // tile row stride (floats): 41 f4, odd -> conflict-free .128
#define MAXN    8192

__device__ float g_cc[MAXN];   // cc[i] = c[i-1], cc[0] = 0
__device__ float g_ia[MAXN];   // 1 / a[i]
__device__ float g_w [MAXN];   // b[i] / a[i], w[N-1] = 0

__global__ void setup_coeffs(const float* __restrict__ a,
                             const float* __restrict__ b,
                             const float* __restrict__ c, int N) {
    int i = blockIdx.x * blockDim.x + threadIdx.x;
    if (i < N) {
        g_cc[i] = (i == 0) ? 0.0f : c[i - 1];
        float ia = 1.0f / a[i];
        g_ia[i] = ia;
        g_w[i]  = (i < N - 1) ? b[i] * ia : 0.0f;
    }
}

__device__ __forceinline__ uint32_t smem_u32(const void* p) {
    return (uint32_t)__cvta_generic_to_shared(p);
}

__device__ __forceinline__ void cp16(uint32_t dst, const float* src) {
    asm volatile("cp.async.cg.shared.global [%0], [%1], 16;\n"
                 :: "r"(dst), "l"(src));
}

__global__ void __launch_bounds__(ROWS)
solve_kernel(const float* __restrict__ x, float* __restrict__ z, int N) {
    __shared__ float tile[ROWS * TS];          // 32*164*4 = 21.0 KB
    __shared__ float cc_s[CW], ia_s[CW], w_s[CW];  // 1.92 KB

    const int lane = threadIdx.x;                   // 0..31
    const int s    = blockIdx.x * L_CHUNK;          // chunk start
    const int c0   = max(s - HALO, 0);              // tile col range [c0, c1)
    const int c1   = min(s + L_CHUNK + HALO, N);
    const int ncol = c1 - c0;                       // 144 or 160, multiple of 16
    const int nf4  = ncol >> 2;                     // 36 or 40 float4 per row
    const int jlo  = s - c0;                        // 0 (first chunk) or 16
    const int r0   = blockIdx.y * ROWS;

    // ---- Fire-and-forget async loads: whole tile + coefficients in one group.
    {
        const float* xb = x + (size_t)r0 * N + c0;
        #pragma unroll 8
        for (int r = 0; r < ROWS; ++r) {
            const float* xr = xb + (size_t)r * N;
            uint32_t dst = smem_u32(tile + r * TS);
            cp16(dst + lane * 16, xr + lane * 4);          // lanes 0..31 always < nf4
            if (lane + 32 < nf4)
                cp16(dst + (lane + 32) * 16, xr + (lane + 32) * 4);
        }
        // Coefficients (c0 is a multiple of 16 floats -> 16B-aligned f4 source).
        {
            uint32_t d_cc = smem_u32(cc_s), d_ia = smem_u32(ia_s), d_w = smem_u32(w_s);
            cp16(d_cc + lane * 16, g_cc + c0 + lane * 4);
            cp16(d_ia + lane * 16, g_ia + c0 + lane * 4);
            cp16(d_w  + lane * 16, g_w  + c0 + lane * 4);
            if (lane + 32 < nf4) {
                cp16(d_cc + (lane + 32) * 16, g_cc + c0 + (lane + 32) * 4);
                cp16(d_ia + (lane + 32) * 16, g_ia + c0 + (lane + 32) * 4);
                cp16(d_w  + (lane + 32) * 16, g_w  + c0 + (lane + 32) * 4);
            }
        }
        asm volatile("cp.async.commit_group;\n" ::: "memory");
        asm volatile("cp.async.wait_group 0;\n" ::: "memory");
    }
    __syncwarp();

    // ---- Per-thread row solve (thread == row), fully in place in the tile row.
    {
        float* tr = tile + lane * TS;

        // Forward: y[i] = x[i] - y[i-1]*cc[i]; store u = y/a (off-chain mul).
        float y = 0.0f;   // exact for c0==0 (cc[0]=0); halo-warmed otherwise
        #pragma unroll 4
        for (int j = 0; j < ncol; j += 4) {
            float4 xv = *(const float4*)(tr + j);
            float4 cv = *(const float4*)(cc_s + j);
            float4 iv = *(const float4*)(ia_s + j);
            float4 u;
            y = fmaf(-y, cv.x, xv.x); u.x = y * iv.x;
            y = fmaf(-y, cv.y, xv.y); u.y = y * iv.y;
            y = fmaf(-y, cv.z, xv.z); u.z = y * iv.z;
            y = fmaf(-y, cv.w, xv.w); u.w = y * iv.w;
            *(float4*)(tr + j) = u;
        }

        // Backward: z[i] = u[i] - w[i]*z[i+1]  (single-FMA 4-cycle chain).
        float zv = 0.0f;  // exact for c1==N (w[N-1]=0); halo-warmed otherwise
        #pragma unroll 4
        for (int j = ncol - 4; j >= jlo; j -= 4) {
            float4 uv = *(const float4*)(tr + j);
            float4 wv = *(const float4*)(w_s + j);
            float4 zo;
            zv = fmaf(-zv, wv.w, uv.w); zo.w = zv;
            zv = fmaf(-zv, wv.z, uv.z); zo.z = zv;
            zv = fmaf(-zv, wv.y, uv.y); zo.y = zv;
            zv = fmaf(-zv, wv.x, uv.x); zo.x = zv;
            *(float4*)(tr + j) = zo;
        }
    }
    __syncwarp();

    // ---- Store interior [jlo, jlo+128): 32 f4 per row == one lane each.
    // LDS.128 consecutive within a row (conflict-free), STG.128 512B/warp.
    {
        float* zb = z + (size_t)r0 * N + s;
        #pragma unroll 8
        for (int r = 0; r < ROWS; ++r) {
            float4 v = *(const float4*)(tile + r * TS + jlo + lane * 4);
            *(float4*)(zb + (size_t)r * N + lane * 4) = v;
        }
    }
}

extern "C" void kernel_launch(void* const* d_in, const int* in_sizes, int n_in,
                              void* d_out, int out_size) {
    const float* x = (const float*)d_in[0];
    const float* a = (const float*)d_in[1];
    const float* b = (const float*)d_in[2];
    const float* c = (const float*)d_in[3];
    float* z = (float*)d_out;

    const int N = in_sizes[1];          // 8192
    const int B = in_sizes[0] / N;      // 4096

    setup_coeffs<<<(N + 255) / 256, 256>>>(a, b, c, N);

    dim3 grid(N / L_CHUNK, B / ROWS);   // 64 x 128 = 8192 blocks
    solve_kernel<<<grid, ROWS>>>(x, z, N);
}

// round 10
// speedup vs baseline: 13.3699x; 1.0323x over previous
#include <cuda_runtime.h>
#include <cstdint>

// Tridiagonal Thomas solve with precomputed LU factors, chunked with
// exponential-decay halos (|c|,|w| <= 1/3 => 0.268^16 ~ 7e-10 warmup error).
//
// R10: one block == one warp == an independent pipeline; chunk shrunk to
// L=64 (+16 halo each side) so smem is ~14 KB/block -> 16 resident
// blocks/SM. 16 decorrelated load(cp.async)->compute->store pipelines per
// SM keep HBM demand continuous; halo re-reads are served from L2
// (neighbors' interior data).

#define L_CHUNK 64
#define HALO    16
#define CW      (L_CHUNK + 2 * HALO)   // 96 columns max per tile
#define ROWS    32                     // rows per block == threads per block
#define TS      100                    // tile row stride (floats): 25 f4, odd -> conflict-free .128
#define MAXN    8192

__device__ float g_cc[MAXN];   // cc[i] = c[i-1], cc[0] = 0
__device__ float g_ia[MAXN];   // 1 / a[i]
__device__ float g_w [MAXN];   // b[i] / a[i], w[N-1] = 0

__global__ void setup_coeffs(const float* __restrict__ a,
                             const float* __restrict__ b,
                             const float* __restrict__ c, int N) {
    int i = blockIdx.x * blockDim.x + threadIdx.x;
    if (i < N) {
        g_cc[i] = (i == 0) ? 0.0f : c[i - 1];
        float ia = 1.0f / a[i];
        g_ia[i] = ia;
        g_w[i]  = (i < N - 1) ? b[i] * ia : 0.0f;
    }
}

__device__ __forceinline__ uint32_t smem_u32(const void* p) {
    return (uint32_t)__cvta_generic_to_shared(p);
}

__device__ __forceinline__ void cp16(uint32_t dst, const float* src) {
    asm volatile("cp.async.cg.shared.global [%0], [%1], 16;\n"
                 :: "r"(dst), "l"(src));
}

__global__ void __launch_bounds__(ROWS)
solve_kernel(const float* __restrict__ x, float* __restrict__ z, int N) {
    __shared__ float tile[ROWS * TS];              // 32*100*4 = 12.5 KB
    __shared__ float cc_s[CW], ia_s[CW], w_s[CW];  // 1.15 KB

    const int lane = threadIdx.x;                   // 0..31
    const int s    = blockIdx.x * L_CHUNK;          // chunk start
    const int c0   = max(s - HALO, 0);              // tile col range [c0, c1)
    const int c1   = min(s + L_CHUNK + HALO, N);
    const int ncol = c1 - c0;                       // 80 or 96, multiple of 16
    const int nf4  = ncol >> 2;                     // 20 or 24 float4 per row (<= 32)
    const int jlo  = s - c0;                        // 0 (first chunk) or 16
    const int r0   = blockIdx.y * ROWS;

    // ---- Fire-and-forget async loads: whole tile + coefficients, one group.
    {
        const float* xb = x + (size_t)r0 * N + c0;
        const bool on = lane < nf4;
        #pragma unroll 8
        for (int r = 0; r < ROWS; ++r) {
            if (on)
                cp16(smem_u32(tile + r * TS) + lane * 16,
                     xb + (size_t)r * N + lane * 4);
        }
        if (on) {   // c0 is a multiple of 16 floats -> 16B-aligned sources
            cp16(smem_u32(cc_s) + lane * 16, g_cc + c0 + lane * 4);
            cp16(smem_u32(ia_s) + lane * 16, g_ia + c0 + lane * 4);
            cp16(smem_u32(w_s)  + lane * 16, g_w  + c0 + lane * 4);
        }
        asm volatile("cp.async.commit_group;\n" ::: "memory");
        asm volatile("cp.async.wait_group 0;\n" ::: "memory");
    }
    __syncwarp();

    // ---- Per-thread row solve (thread == row), in place in the tile row.
    {
        float* tr = tile + lane * TS;

        // Forward: y[i] = x[i] - y[i-1]*cc[i]; store u = y/a (off-chain mul).
        float y = 0.0f;   // exact for c0==0 (cc[0]=0); halo-warmed otherwise
        #pragma unroll 4
        for (int j = 0; j < ncol; j += 4) {
            float4 xv = *(const float4*)(tr + j);
            float4 cv = *(const float4*)(cc_s + j);
            float4 iv = *(const float4*)(ia_s + j);
            float4 u;
            y = fmaf(-y, cv.x, xv.x); u.x = y * iv.x;
            y = fmaf(-y, cv.y, xv.y); u.y = y * iv.y;
            y = fmaf(-y, cv.z, xv.z); u.z = y * iv.z;
            y = fmaf(-y, cv.w, xv.w); u.w = y * iv.w;
            *(float4*)(tr + j) = u;
        }

        // Backward: z[i] = u[i] - w[i]*z[i+1]  (single-FMA 4-cycle chain).
        float zv = 0.0f;  // exact for c1==N (w[N-1]=0); halo-warmed otherwise
        #pragma unroll 4
        for (int j = ncol - 4; j >= jlo; j -= 4) {
            float4 uv = *(const float4*)(tr + j);
            float4 wv = *(const float4*)(w_s + j);
            float4 zo;
            zv = fmaf(-zv, wv.w, uv.w); zo.w = zv;
            zv = fmaf(-zv, wv.z, uv.z); zo.z = zv;
            zv = fmaf(-zv, wv.y, uv.y); zo.y = zv;
            zv = fmaf(-zv, wv.x, uv.x); zo.x = zv;
            *(float4*)(tr + j) = zo;
        }
    }
    __syncwarp();

    // ---- Store interior [jlo, jlo+64): 16 f4 per row, 2 rows per warp-iter.
    // LDS.128 conflict-free (row stride 25 f4, odd), STG.128 coalesced.
    {
        float* zb = z + (size_t)r0 * N + s;
        const int nout = ROWS * (L_CHUNK / 4);     // 512
        #pragma unroll 16
        for (int i = lane; i < nout; i += 32) {
            int row = i >> 4;
            int c4  = i & 15;
            float4 v = *(const float4*)(tile + row * TS + jlo + c4 * 4);
            *(float4*)(zb + (size_t)row * N + c4 * 4) = v;
        }
    }
}

extern "C" void kernel_launch(void* const* d_in, const int* in_sizes, int n_in,
                              void* d_out, int out_size) {
    const float* x = (const float*)d_in[0];
    const float* a = (const float*)d_in[1];
    const float* b = (const float*)d_in[2];
    const float* c = (const float*)d_in[3];
    float* z = (float*)d_out;

    const int N = in_sizes[1];          // 8192
    const int B = in_sizes[0] / N;      // 4096

    setup_coeffs<<<(N + 255) / 256, 256>>>(a, b, c, N);

    dim3 grid(N / L_CHUNK, B / ROWS);   // 128 x 128 = 16384 blocks
    solve_kernel<<<grid, ROWS>>>(x, z, N);
}